// round 14
// baseline (speedup 1.0000x reference)
#include <cuda_runtime.h>
#include <cuda_bf16.h>
#include <cstdint>

typedef unsigned long long ull;

constexpr int Bn = 128;
constexpr int Tn = 1024;
constexpr int In = 256;
constexpr int Hn = 512;

// rnn smem layout (bytes)
constexpr int WS_BYTES  = 32 * 256 * 16;          // Wh smem (col-B weights): 131072
constexpr int HP_PAIR   = 520;                    // padded ull per (buf,pair)
constexpr int HP_OFF    = WS_BYTES;
constexpr int HP_BYTES  = 2 * 2 * HP_PAIR * 8;    // 16640
constexpr int PART_OFF  = HP_OFF + HP_BYTES;      // partials [2 buf][4 src][128 col][2 pair] ull
constexpr int PART_BYTES= 2 * 4 * 128 * 2 * 8;    // 16384
constexpr int MB_OFF    = PART_OFF + PART_BYTES;  // mbar[2 buf][4 src][2 half]
constexpr int SMEM_RNN  = MB_OFF + 16 * 8;

__device__ __forceinline__ ull pack2f(float x, float y) {
    ull r; asm("mov.b64 %0, {%1, %2};" : "=l"(r) : "f"(x), "f"(y)); return r;
}
__device__ __forceinline__ float2 unpack2f(ull v) {
    float2 r; asm("mov.b64 {%0, %1}, %2;" : "=f"(r.x), "=f"(r.y) : "l"(v)); return r;
}
__device__ __forceinline__ ull splat2f(float x) {
    ull r; asm("mov.b64 %0, {%1, %1};" : "=l"(r) : "f"(x)); return r;
}
__device__ __forceinline__ void ffma2(ull& a, ull x, ull y) {
    asm("fma.rn.f32x2 %0, %1, %2, %0;" : "+l"(a) : "l"(x), "l"(y));
}
__device__ __forceinline__ ull packadd(ull e, ull o) {
    float2 a = unpack2f(e), b = unpack2f(o);
    return pack2f(a.x + b.x, a.y + b.y);
}
__device__ __forceinline__ float sigmoidf_fast(float z) {
    return __fdividef(1.0f, 1.0f + __expf(-z));
}
__device__ __forceinline__ uint32_t smem_u32(const void* p) {
    return (uint32_t)__cvta_generic_to_shared(p);
}
__device__ __forceinline__ void mbar_wait(uint32_t maddr, uint32_t phase) {
    uint32_t done;
    do {
        asm volatile(
            "{\n\t.reg .pred p;\n\t"
            "mbarrier.try_wait.parity.acquire.cluster.shared::cta.b64 p, [%1], %2, 0x989680;\n\t"
            "selp.b32 %0, 1, 0, p;\n\t}"
            : "=r"(done) : "r"(maddr), "r"(phase) : "memory");
    } while (!done);
}

// ---------------------------------------------------------------------------
// Kernel 1: igates via bf16 tensor cores, 3-term split (round-13 winner).
// ---------------------------------------------------------------------------
constexpr int GI_BM = 128, GI_BN = 64, GI_BK = 32;
constexpr int GI_XS = GI_BK / 2 + 4;

__device__ __forceinline__ void mma_bf16(float* c, const unsigned* a, const unsigned* b) {
    asm volatile(
        "mma.sync.aligned.m16n8k16.row.col.f32.bf16.bf16.f32 "
        "{%0,%1,%2,%3}, {%4,%5,%6,%7}, {%8,%9}, {%0,%1,%2,%3};"
        : "+f"(c[0]), "+f"(c[1]), "+f"(c[2]), "+f"(c[3])
        : "r"(a[0]), "r"(a[1]), "r"(a[2]), "r"(a[3]), "r"(b[0]), "r"(b[1]));
}
__device__ __forceinline__ unsigned packbf(float f0, float f1) {
    __nv_bfloat162 t = __floats2bfloat162_rn(f0, f1);
    return reinterpret_cast<unsigned&>(t);
}

__global__ __launch_bounds__(256) void igates_tc_kernel(
    const float* __restrict__ X,
    const float* __restrict__ Wi,
    const float* __restrict__ bi,
    float* __restrict__ out)
{
    __shared__ unsigned Xh[GI_BM][GI_XS], Xl[GI_BM][GI_XS];
    __shared__ unsigned Wh[GI_BN][GI_XS], Wl[GI_BN][GI_XS];

    const int tid  = threadIdx.x;
    const int lane = tid & 31;
    const int warp = tid >> 5;
    const int wm   = warp & 3;
    const int wn   = warp >> 2;
    const int m0   = blockIdx.y * GI_BM;
    const int n0   = blockIdx.x * GI_BN;
    const int gr   = lane >> 2;
    const int gc   = lane & 3;

    float acc[2][4][4] = {};

    for (int k0 = 0; k0 < In; k0 += GI_BK) {
        #pragma unroll
        for (int i = 0; i < 4; i++) {
            int idx = tid + 256 * i;
            int r   = idx >> 3;
            int c4  = idx & 7;
            float4 v = *(const float4*)(X + (size_t)(m0 + r) * In + k0 + c4 * 4);
            float hx = __bfloat162float(__float2bfloat16(v.x));
            float hy = __bfloat162float(__float2bfloat16(v.y));
            float hz = __bfloat162float(__float2bfloat16(v.z));
            float hw = __bfloat162float(__float2bfloat16(v.w));
            Xh[r][c4*2]   = packbf(hx, hy);
            Xh[r][c4*2+1] = packbf(hz, hw);
            Xl[r][c4*2]   = packbf(v.x - hx, v.y - hy);
            Xl[r][c4*2+1] = packbf(v.z - hz, v.w - hw);
        }
        #pragma unroll
        for (int i = 0; i < 2; i++) {
            int idx = tid + 256 * i;
            int r   = idx >> 3;
            int c4  = idx & 7;
            float4 v = *(const float4*)(Wi + (size_t)(n0 + r) * In + k0 + c4 * 4);
            float hx = __bfloat162float(__float2bfloat16(v.x));
            float hy = __bfloat162float(__float2bfloat16(v.y));
            float hz = __bfloat162float(__float2bfloat16(v.z));
            float hw = __bfloat162float(__float2bfloat16(v.w));
            Wh[r][c4*2]   = packbf(hx, hy);
            Wh[r][c4*2+1] = packbf(hz, hw);
            Wl[r][c4*2]   = packbf(v.x - hx, v.y - hy);
            Wl[r][c4*2+1] = packbf(v.z - hz, v.w - hw);
        }
        __syncthreads();

        #pragma unroll
        for (int kb = 0; kb < 2; kb++) {
            const int c = kb * 8 + gc;
            unsigned ah[2][4], al[2][4];
            #pragma unroll
            for (int mt = 0; mt < 2; mt++) {
                int r = wm * 32 + mt * 16 + gr;
                ah[mt][0] = Xh[r][c];     ah[mt][1] = Xh[r+8][c];
                ah[mt][2] = Xh[r][c+4];   ah[mt][3] = Xh[r+8][c+4];
                al[mt][0] = Xl[r][c];     al[mt][1] = Xl[r+8][c];
                al[mt][2] = Xl[r][c+4];   al[mt][3] = Xl[r+8][c+4];
            }
            unsigned bh[4][2], bl[4][2];
            #pragma unroll
            for (int nt = 0; nt < 4; nt++) {
                int n = wn * 32 + nt * 8 + gr;
                bh[nt][0] = Wh[n][c];  bh[nt][1] = Wh[n][c+4];
                bl[nt][0] = Wl[n][c];  bl[nt][1] = Wl[n][c+4];
            }
            #pragma unroll
            for (int mt = 0; mt < 2; mt++)
                #pragma unroll
                for (int nt = 0; nt < 4; nt++) {
                    mma_bf16(acc[mt][nt], ah[mt], bh[nt]);
                    mma_bf16(acc[mt][nt], ah[mt], bl[nt]);
                    mma_bf16(acc[mt][nt], al[mt], bh[nt]);
                }
        }
        __syncthreads();
    }

    #pragma unroll
    for (int mt = 0; mt < 2; mt++) {
        int r = m0 + wm * 32 + mt * 16 + gr;
        #pragma unroll
        for (int nt = 0; nt < 4; nt++) {
            int cc = n0 + wn * 32 + nt * 8 + 2 * gc;
            float b0 = bi[cc], b1 = bi[cc + 1];
            float2 o0 = make_float2(acc[mt][nt][0] + b0, acc[mt][nt][1] + b1);
            float2 o1 = make_float2(acc[mt][nt][2] + b0, acc[mt][nt][3] + b1);
            *(float2*)(out + (size_t)r       * Hn + cc) = o0;
            *(float2*)(out + (size_t)(r + 8) * Hn + cc) = o1;
        }
    }
}

// ---------------------------------------------------------------------------
// Kernel 2: recurrence, 32 clusters x 4 CTAs, one-source-per-warp.
//   Warp w: c = w>>1 (source chunk, k [128c,128c+128)), hh = w&1 (cols
//   [64hh, 64hh+64) of this CTA's slice). Thread: cols A=64hh+lane,
//   B=A+32; weights colA in regs (32 f4), colB in smem. h LDS broadcast
//   (all lanes same k) reused for 2 cols. Consumer: 2 waits on per-
//   (src,half) mbarriers (count 4), 64-k pipelining. k-reduction across
//   4 source-warps via double-buffered smem partials + 128-thread named
//   barrier (id hh+1). Epilogue thread = (col_e = 64hh+32(c&1)+lane,
//   pair pr_e = c>>1): sum 4 partials, sigmoid, push to 4 ranks,
//   __syncwarp, lane0 arrives at mbar[nb][crank][hh] on 4 ranks. No CTA
//   __syncthreads in the loop. Trailing cluster barrier required.
// ---------------------------------------------------------------------------
__global__ __launch_bounds__(256, 1) __cluster_dims__(4, 1, 1)
void rnn_kernel(
    float* __restrict__ out,
    const float* __restrict__ hidden,
    const float* __restrict__ Wh,
    const float* __restrict__ bh)
{
    extern __shared__ char sm[];
    float4* Wsm  = (float4*)sm;                  // [32][256] col-B weights
    ull*    hpb  = (ull*)(sm + HP_OFF);          // [2 buf][2 pair][520]
    ull*    part = (ull*)(sm + PART_OFF);        // [2][4][128][2]
    ull*    mbar = (ull*)(sm + MB_OFF);          // [2][4][2]

    const int tid  = threadIdx.x;
    const int lane = tid & 31;
    const int warp = tid >> 5;                   // 0..7
    const int c    = warp >> 1;                  // source chunk 0..3
    const int hh   = warp & 1;                   // column half
    uint32_t crank; asm("mov.u32 %0, %%cluster_ctarank;" : "=r"(crank));
    const int g    = blockIdx.x >> 2;

    const int jA   = 64 * hh + lane;             // compute col A (local)
    const int gjA  = (int)crank * 128 + jA;
    const int gjB  = gjA + 32;

    // epilogue identity
    const int col_e = 64 * hh + 32 * (c & 1) + lane;
    const int je    = (int)crank * 128 + col_e;
    const int pr_e  = c >> 1;
    const float bhj = bh[je];
    const int b0    = 4 * g + 2 * pr_e;
    const int jidx_e= je + ((je >> 8) << 3);

    float* __restrict__ hl = out + (size_t)Bn * Tn * Hn;

    // ---- weights: colA chunk -> 32 f4 regs; colB chunk -> smem ----
    float4 W4[32];
    {
        const float4* wpA = (const float4*)(Wh + (size_t)gjA * Hn + 128 * c);
        #pragma unroll
        for (int u = 0; u < 32; u++) W4[u] = wpA[u];
        const float4* wpB = (const float4*)(Wh + (size_t)gjB * Hn + 128 * c);
        #pragma unroll
        for (int u = 0; u < 32; u++) Wsm[u * 256 + tid] = wpB[u];
    }

    // ---- mbarrier init: [2 buf][4 src][2 half], count 4 ----
    if (tid == 0) {
        #pragma unroll
        for (int m = 0; m < 16; m++) {
            asm volatile("mbarrier.init.shared.b64 [%0], %1;"
                         :: "r"(smem_u32(&mbar[m])), "r"(4u) : "memory");
        }
    }

    // ---- stage initial hidden into hp buf 0 ----
    for (int i = tid; i < 1024; i += 256) {
        int pair = i >> 9, col = i & 511;
        int idx  = col + ((col >> 8) << 3);
        hpb[pair * HP_PAIR + idx] =
            pack2f(hidden[(4 * g + 2 * pair) * Hn + col],
                   hidden[(4 * g + 2 * pair + 1) * Hn + col]);
    }
    __syncthreads();

    // cluster-wide: init + staging complete before any remote store/arrive
    asm volatile("barrier.cluster.arrive.aligned;" ::: "memory");
    asm volatile("barrier.cluster.wait.aligned;"   ::: "memory");

    // ---- remote addresses ----
    const uint32_t hp_u32 = smem_u32(hpb);
    const uint32_t mb_u32 = smem_u32(mbar);
    uint32_t rhp[4], rmbA[4], rmbB[4];
    #pragma unroll
    for (int r = 0; r < 4; r++) {
        asm("mapa.shared::cluster.u32 %0, %1, %2;" : "=r"(rhp[r]) : "r"(hp_u32), "r"(r));
        // mbar[buf][crank][hh] at rank r, for buf 0 and 1
        uint32_t l0 = mb_u32 + ((0u * 4u + crank) * 2u + (uint32_t)hh) * 8u;
        uint32_t l1 = mb_u32 + ((1u * 4u + crank) * 2u + (uint32_t)hh) * 8u;
        asm("mapa.shared::cluster.u32 %0, %1, %2;" : "=r"(rmbA[r]) : "r"(l0), "r"(r));
        asm("mapa.shared::cluster.u32 %0, %1, %2;" : "=r"(rmbB[r]) : "r"(l1), "r"(r));
    }
    const uint32_t poff = (uint32_t)(pr_e * HP_PAIR + jidx_e) * 8u;
    const int off_c = 128 * c + ((c >> 1) << 3);    // chunk base in hp (padded)
    const float4* ws = Wsm + tid;

    const size_t orow0 = (size_t)b0       * (Tn * Hn);
    const size_t orow1 = (size_t)(b0 + 1) * (Tn * Hn);

    for (int t = 0; t < Tn; t++) {
        const int cur = t & 1;
        const int nb  = cur ^ 1;
        const uint32_t phase = (uint32_t)((t - 1) >> 1) & 1u;

        // igate prefetch (independent of h; overlaps waits + compute)
        const float ig0 = __ldcg(out + orow0 + (size_t)t * Hn + je);
        const float ig1 = __ldcg(out + orow1 + (size_t)t * Hn + je);

        const ull* hp0 = hpb + cur * (2 * HP_PAIR) + 0 * HP_PAIR + off_c;
        const ull* hp1 = hpb + cur * (2 * HP_PAIR) + 1 * HP_PAIR + off_c;
        ull aA0e = 0, aA0o = 0, aA1e = 0, aA1o = 0;
        ull aB0e = 0, aB0o = 0, aB1e = 0, aB1o = 0;

        #pragma unroll
        for (int ss = 0; ss < 2; ss++) {
            if (t > 0) {
                mbar_wait(mb_u32 + (uint32_t)((cur * 4 + c) * 2 + ss) * 8u, phase);
            }
            #pragma unroll
            for (int u = 16 * ss; u < 16 * ss + 16; u++) {
                float4 wA = W4[u];
                float4 wB = ws[u * 256];
                ulonglong2 h0a = *(const ulonglong2*)(hp0 + 4*u);
                ulonglong2 h0b = *(const ulonglong2*)(hp0 + 4*u + 2);
                ulonglong2 h1a = *(const ulonglong2*)(hp1 + 4*u);
                ulonglong2 h1b = *(const ulonglong2*)(hp1 + 4*u + 2);
                ull ax = splat2f(wA.x), ay = splat2f(wA.y),
                    az = splat2f(wA.z), aw = splat2f(wA.w);
                ffma2(aA0e, ax, h0a.x); ffma2(aA0o, ay, h0a.y);
                ffma2(aA0e, az, h0b.x); ffma2(aA0o, aw, h0b.y);
                ffma2(aA1e, ax, h1a.x); ffma2(aA1o, ay, h1a.y);
                ffma2(aA1e, az, h1b.x); ffma2(aA1o, aw, h1b.y);
                ull bx = splat2f(wB.x), by = splat2f(wB.y),
                    bz = splat2f(wB.z), bw = splat2f(wB.w);
                ffma2(aB0e, bx, h0a.x); ffma2(aB0o, by, h0a.y);
                ffma2(aB0e, bz, h0b.x); ffma2(aB0o, bw, h0b.y);
                ffma2(aB1e, bx, h1a.x); ffma2(aB1o, by, h1a.y);
                ffma2(aB1e, bz, h1b.x); ffma2(aB1o, bw, h1b.y);
            }
        }

        // ---- store partials [cur][c][col][pair] ----
        {
            ull* pp = part + (size_t)((cur * 4 + c) * 128) * 2;
            ulonglong2 vA = make_ulonglong2(packadd(aA0e, aA0o), packadd(aA1e, aA1o));
            ulonglong2 vB = make_ulonglong2(packadd(aB0e, aB0o), packadd(aB1e, aB1o));
            *(ulonglong2*)(pp + (size_t)jA * 2)        = vA;
            *(ulonglong2*)(pp + (size_t)(jA + 32) * 2) = vB;
        }

        // ---- half-group reduction barrier (4 warps, 128 threads) ----
        asm volatile("bar.sync %0, %1;" :: "r"(hh + 1), "r"(128) : "memory");

        // ---- epilogue: sum 4 source partials, sigmoid ----
        float sx = 0.f, sy = 0.f;
        #pragma unroll
        for (int s = 0; s < 4; s++) {
            float2 v = unpack2f(part[(size_t)((cur * 4 + s) * 128 + col_e) * 2 + pr_e]);
            sx += v.x; sy += v.y;
        }
        float h0v = sigmoidf_fast(sx + ig0 + bhj);
        float h1v = sigmoidf_fast(sy + ig1 + bhj);

        // ---- DSMEM push to all 4 CTAs' hp[nb] ----
        const ull v = pack2f(h0v, h1v);
        const uint32_t boff = (uint32_t)(nb * 2 * HP_PAIR) * 8u + poff;
        #pragma unroll
        for (int r = 0; r < 4; r++) {
            asm volatile("st.shared::cluster.u64 [%0], %1;"
                         :: "r"(rhp[r] + boff), "l"(v) : "memory");
        }

        // ---- per-warp arrival at mbar[nb][crank][hh] on 4 ranks ----
        __syncwarp();
        if (lane == 0) {
            #pragma unroll
            for (int r = 0; r < 4; r++) {
                asm volatile("mbarrier.arrive.release.cluster.shared::cluster.b64 _, [%0];"
                             :: "r"(nb ? rmbB[r] : rmbA[r]) : "memory");
            }
        }

        // ---- global stores (off the inter-CTA critical path) ----
        out[orow0 + (size_t)t * Hn + je] = h0v;
        out[orow1 + (size_t)t * Hn + je] = h1v;
        if (t == Tn - 1) {
            hl[b0 * Hn + je]       = h0v;
            hl[(b0 + 1) * Hn + je] = h1v;
        }
    }

    // ---- REQUIRED: peers' DSMEM stores / arrivals may still target our SMEM
    asm volatile("barrier.cluster.arrive.aligned;" ::: "memory");
    asm volatile("barrier.cluster.wait.aligned;"   ::: "memory");
}

// ---------------------------------------------------------------------------
// Launch
// ---------------------------------------------------------------------------
extern "C" void kernel_launch(void* const* d_in, const int* in_sizes, int n_in,
                              void* d_out, int out_size)
{
    const float* x      = (const float*)d_in[0];   // [B, T, I]
    const float* hidden = (const float*)d_in[1];   // [B, H]
    const float* Wi     = (const float*)d_in[2];   // [H, I]
    const float* bi     = (const float*)d_in[3];   // [H]
    const float* Wh     = (const float*)d_in[4];   // [H, H]
    const float* bh     = (const float*)d_in[5];   // [H]
    float* out = (float*)d_out;                    // [B,T,H] then [B,H] h_last

    dim3 g1(Hn / GI_BN, (Bn * Tn) / GI_BM);
    igates_tc_kernel<<<g1, 256>>>(x, Wi, bi, out);

    static bool attr_set = false;
    if (!attr_set) {
        cudaFuncSetAttribute(rnn_kernel,
                             cudaFuncAttributeMaxDynamicSharedMemorySize, SMEM_RNN);
        attr_set = true;
    }
    rnn_kernel<<<128, 256, SMEM_RNN>>>(out, hidden, Wh, bh);
}